// round 8
// baseline (speedup 1.0000x reference)
#include <cuda_runtime.h>
#include <cuda_bf16.h>
#include <cstdint>

// ---------------- problem constants ----------------
#define BB    2048
#define F1N   10
#define F2N   25
#define NTOK  261
#define XR4   32                 // float4 per 128-float x row

// ---------------- scratch (device globals, allocation-free) ----------------
__device__ __align__(16) __nv_bfloat16 g_A2h[BB * 512];
__device__ __align__(16) __nv_bfloat16 g_A2l[BB * 512];
__device__ __align__(16) __nv_bfloat16 g_W1hT[256 * 256];
__device__ __align__(16) __nv_bfloat16 g_W1lT[256 * 256];
__device__ __align__(16) __nv_bfloat16 g_W2hT[256 * 512];
__device__ __align__(16) __nv_bfloat16 g_W2lT[256 * 512];

// ---------------- PTX helpers (base sm_100-safe) ----------------
__device__ __forceinline__ uint32_t smem_u32(const void* p) {
    uint32_t a;
    asm("{ .reg .u64 t; cvta.to.shared.u64 t, %1; cvt.u32.u64 %0, t; }" : "=r"(a) : "l"(p));
    return a;
}
__device__ __forceinline__ void cp16(uint32_t s, const void* g) {
    asm volatile("cp.async.cg.shared.global [%0], [%1], 16;" :: "r"(s), "l"(g));
}
#define CP_COMMIT() asm volatile("cp.async.commit_group;" ::: "memory")
#define CP_WAIT(n)  asm volatile("cp.async.wait_group %0;" :: "n"(n) : "memory")

__device__ __forceinline__ void ldsm4(uint32_t* r, uint32_t addr) {
    asm volatile("ldmatrix.sync.aligned.m8n8.x4.shared.b16 {%0,%1,%2,%3}, [%4];"
                 : "=r"(r[0]), "=r"(r[1]), "=r"(r[2]), "=r"(r[3]) : "r"(addr));
}
__device__ __forceinline__ void mma16816(float* c, const uint32_t* a, const uint32_t* b) {
    asm volatile(
        "mma.sync.aligned.m16n8k16.row.col.f32.bf16.bf16.f32 "
        "{%0,%1,%2,%3}, {%4,%5,%6,%7}, {%8,%9}, {%0,%1,%2,%3};"
        : "+f"(c[0]), "+f"(c[1]), "+f"(c[2]), "+f"(c[3])
        : "r"(a[0]), "r"(a[1]), "r"(a[2]), "r"(a[3]), "r"(b[0]), "r"(b[1]));
}

// ---------------- bf16 split helpers ----------------
__device__ __forceinline__ void split1(float w, unsigned short& h, unsigned short& l) {
    __nv_bfloat16 hb = __float2bfloat16_rn(w);
    float r = w - __bfloat162float(hb);
    __nv_bfloat16 lb = __float2bfloat16_rn(r);
    h = __bfloat16_as_ushort(hb);
    l = __bfloat16_as_ushort(lb);
}
__device__ __forceinline__ void split_store2(__nv_bfloat16* H, __nv_bfloat16* L,
                                             size_t idx, float a, float b) {
    unsigned short h0, l0, h1, l1;
    split1(a, h0, l0);
    split1(b, h1, l1);
    *reinterpret_cast<uint32_t*>(H + idx) = (uint32_t)h0 | ((uint32_t)h1 << 16);
    *reinterpret_cast<uint32_t*>(L + idx) = (uint32_t)l0 | ((uint32_t)l1 << 16);
}

// ---------------- K0: tiled weight transpose + split ----------------
__global__ __launch_bounds__(256)
void k_convw(const float* __restrict__ W1, const float* __restrict__ W2) {
    __shared__ float tile[32][33];
    int t = blockIdx.x;
    const float* W;
    __nv_bfloat16 *OH, *OL;
    int KD, ND, tk, tn;
    if (t < 64) {
        W = W1; OH = g_W1hT; OL = g_W1lT; KD = 256; ND = 256;
        tk = t >> 3; tn = t & 7;
    } else {
        t -= 64;
        W = W2; OH = g_W2hT; OL = g_W2lT; KD = 512; ND = 256;
        tk = t >> 3; tn = t & 7;
    }
    int x = threadIdx.x, y0 = threadIdx.y;
#pragma unroll
    for (int yy = 0; yy < 4; yy++) {
        int k = tk * 32 + y0 * 4 + yy;
        tile[y0 * 4 + yy][x] = W[(size_t)k * ND + tn * 32 + x];
    }
    __syncthreads();
#pragma unroll
    for (int yy = 0; yy < 4; yy++) {
        int n = tn * 32 + y0 * 4 + yy;
        float v = tile[x][y0 * 4 + yy];
        unsigned short h, l;
        split1(v, h, l);
        size_t o = (size_t)n * KD + tk * 32 + x;
        OH[o] = __ushort_as_bfloat16(h);
        OL[o] = __ushort_as_bfloat16(l);
    }
}

// ---------------- fused1: reduce + GEMM1 + pool, warp-specialized pipeline ----------------
// CTA: 4 batch groups (48 A rows: [h0,10*h1,dummy] x4), BN=256, K = 4 chunks of 64.
// 640 thr = 12 consumer warps (3M x 4N, tile 16x64) + 8 producer warps (256 thr).
// smem: A stages 2x12KB, B stages 2x64KB, msum 2KB; epilogue fp32 [48][258] reuses front.
static constexpr int AHS0 = 0;                 // stage s: AH = s*12288, AL = s*12288+6144
static constexpr int BS0  = 24576;             // stage s: BH = 24576+s*65536, BL = +32768
static constexpr int MS   = 24576 + 2 * 65536; // 155648, msum 512 floats
static constexpr int SMEM_FU = MS + 2048;      // 157696
static constexpr int SROW = 258;

__global__ __launch_bounds__(640)
void fused1(const float4* __restrict__ x4, const float* __restrict__ bias) {
    extern __shared__ char smem[];
    const uint32_t sb = smem_u32(smem);
    float* msum = reinterpret_cast<float*>(smem + MS);
    const int tid = threadIdx.x, wid = tid >> 5, lane = tid & 31;
    const int b0 = blockIdx.x * 4;

    // ---- producer: build A chunk + prefetch B chunk into stage s ----
    auto storeA = [&](int s, int row, int tsub, float4 v) {
        unsigned short hs[4], ls[4];
        float f[4] = {v.x, v.y, v.z, v.w};
#pragma unroll
        for (int e = 0; e < 4; e++) split1(f[e], hs[e], ls[e]);
        uint2 hv = make_uint2((uint32_t)hs[0] | ((uint32_t)hs[1] << 16),
                              (uint32_t)hs[2] | ((uint32_t)hs[3] << 16));
        uint2 lv = make_uint2((uint32_t)ls[0] | ((uint32_t)ls[1] << 16),
                              (uint32_t)ls[2] | ((uint32_t)ls[3] << 16));
        int cc = tsub >> 1;
        uint32_t off = row * 128 + ((cc ^ (row & 7)) << 4) + (tsub & 1) * 8;
        char* ab = smem + s * 12288;
        *reinterpret_cast<uint2*>(ab + off) = hv;
        *reinterpret_cast<uint2*>(ab + 6144 + off) = lv;
    };

    auto produce = [&](int c, int s) {
        const int ptid = tid - 384;  // 0..255
        // B prefetch (cp.async): 2048 16B pieces per array
        const uint32_t bh = sb + BS0 + s * 65536;
#pragma unroll
        for (int i = ptid; i < 2048; i += 256) {
            int r = i >> 3, cc = i & 7;
            uint32_t sw = r * 128 + ((cc ^ (r & 7)) << 4);
            size_t go = (size_t)r * 256 + c * 64 + cc * 8;
            cp16(bh + sw, g_W1hT + go);
            cp16(bh + 32768 + sw, g_W1lT + go);
        }
        CP_COMMIT();

        if (c < 2) {
            // self half: seed + hop1 copies, hop1 sum -> msum
            if (ptid < 64) {
                int tsub = ptid & 15, g = ptid >> 4;
                const float4* px = x4 + (size_t)(b0 + g) * (NTOK * XR4) + c * 16 + tsub;
                storeA(s, g * 12, tsub, px[0]);  // seed
                float4 sm = make_float4(0.f, 0.f, 0.f, 0.f);
#pragma unroll
                for (int f = 1; f <= F1N; f++) {
                    float4 v = px[(size_t)f * XR4];
                    storeA(s, g * 12 + f, tsub, v);
                    sm.x += v.x; sm.y += v.y; sm.z += v.z; sm.w += v.w;
                }
                *reinterpret_cast<float4*>(&msum[(c * 4 + g) * 64 + tsub * 4]) = sm;
                storeA(s, g * 12 + 11, tsub, make_float4(0.f, 0.f, 0.f, 0.f));
            }
        } else {
            // mean half: stream hop2 (the big read), h0 mean from msum, dummy zero
            const int xc = (c - 2) * 16;
#pragma unroll 1
            for (int i = ptid; i < 640; i += 256) {
                int tsub = i & 15;
                int gf = i >> 4;              // 0..39
                int f = gf % F1N, g = gf / F1N;
                const float4* px = x4 + (size_t)(b0 + g) * (NTOK * XR4)
                                   + (size_t)(1 + F1N + f * F2N) * XR4 + xc + tsub;
                float4 s0 = make_float4(0.f, 0.f, 0.f, 0.f);
                float4 s1 = s0, s2 = s0, s3 = s0, s4 = s0;
#pragma unroll
                for (int k = 0; k < F2N; k += 5) {
                    float4 v0 = px[(size_t)k * XR4];
                    float4 v1 = px[(size_t)(k + 1) * XR4];
                    float4 v2 = px[(size_t)(k + 2) * XR4];
                    float4 v3 = px[(size_t)(k + 3) * XR4];
                    float4 v4 = px[(size_t)(k + 4) * XR4];
                    s0.x += v0.x; s0.y += v0.y; s0.z += v0.z; s0.w += v0.w;
                    s1.x += v1.x; s1.y += v1.y; s1.z += v1.z; s1.w += v1.w;
                    s2.x += v2.x; s2.y += v2.y; s2.z += v2.z; s2.w += v2.w;
                    s3.x += v3.x; s3.y += v3.y; s3.z += v3.z; s3.w += v3.w;
                    s4.x += v4.x; s4.y += v4.y; s4.z += v4.z; s4.w += v4.w;
                }
                const float inv = 1.0f / (float)F2N;
                storeA(s, g * 12 + 1 + f, tsub,
                       make_float4((s0.x + s1.x + s2.x + s3.x + s4.x) * inv,
                                   (s0.y + s1.y + s2.y + s3.y + s4.y) * inv,
                                   (s0.z + s1.z + s2.z + s3.z + s4.z) * inv,
                                   (s0.w + s1.w + s2.w + s3.w + s4.w) * inv));
            }
            if (ptid < 64) {
                int tsub = ptid & 15, g = ptid >> 4;
                float4 sm = *reinterpret_cast<const float4*>(
                    &msum[((c - 2) * 4 + g) * 64 + tsub * 4]);
                const float inv = 1.0f / (float)F1N;
                storeA(s, g * 12, tsub,
                       make_float4(sm.x * inv, sm.y * inv, sm.z * inv, sm.w * inv));
                storeA(s, g * 12 + 11, tsub, make_float4(0.f, 0.f, 0.f, 0.f));
            }
        }
        CP_WAIT(0);
    };

    // ---- consumer state ----
    const int wm = (wid >> 2) * 16;     // 0,16,32 (wid 0..11)
    const int wn = (wid & 3) * 64;
    float acc[8][4];
#pragma unroll
    for (int j = 0; j < 8; j++)
#pragma unroll
        for (int q = 0; q < 4; q++) acc[j][q] = 0.f;

    auto domma = [&](int s) {
        const uint32_t ah_off = sb + s * 12288;
        const uint32_t al_off = ah_off + 6144;
        const uint32_t bh_off = sb + BS0 + s * 65536;
        const uint32_t bl_off = bh_off + 32768;
#pragma unroll
        for (int k16 = 0; k16 < 4; k16++) {
            const int cc = k16 * 2 + (lane >> 4);
            uint32_t ah[4], al[4];
            {
                int r = wm + (lane & 15);
                uint32_t ad = r * 128 + ((cc ^ (r & 7)) << 4);
                ldsm4(ah, ah_off + ad);
                ldsm4(al, al_off + ad);
            }
#pragma unroll
            for (int ni = 0; ni < 4; ni++) {
                uint32_t bh[4], bl[4];
                int r = wn + ni * 16 + (lane & 15);
                uint32_t ad = r * 128 + ((cc ^ (r & 7)) << 4);
                ldsm4(bh, bh_off + ad);
                ldsm4(bl, bl_off + ad);
#pragma unroll
                for (int jj = 0; jj < 2; jj++) {
                    int j = ni * 2 + jj;
                    uint32_t bfh[2] = {bh[jj], bh[jj + 2]};
                    uint32_t bfl[2] = {bl[jj], bl[jj + 2]};
                    mma16816(acc[j], ah, bfh);
                    mma16816(acc[j], ah, bfl);
                    mma16816(acc[j], al, bfh);
                }
            }
        }
    };

    // ---- pipeline: producers fill c while consumers mma c-1 ----
    if (wid >= 12) produce(0, 0);
    __syncthreads();
#pragma unroll
    for (int c = 1; c < 4; c++) {
        if (wid >= 12) produce(c, c & 1);
        else domma((c - 1) & 1);
        __syncthreads();
    }
    if (wid < 12) domma(1);
    __syncthreads();

    // ---- epilogue: acc (+bias, ReLU) -> smem fp32 [48][258] ----
    float* sacc = reinterpret_cast<float*>(smem);
    if (wid < 12) {
        const int g4 = lane >> 2, q = lane & 3;
#pragma unroll
        for (int j = 0; j < 8; j++) {
            int col = wn + j * 8 + 2 * q;
            float bx = __ldg(bias + col), by = __ldg(bias + col + 1);
            int r = wm + g4;
            sacc[r * SROW + col]           = fmaxf(acc[j][0] + bx, 0.f);
            sacc[r * SROW + col + 1]       = fmaxf(acc[j][1] + by, 0.f);
            sacc[(r + 8) * SROW + col]     = fmaxf(acc[j][2] + bx, 0.f);
            sacc[(r + 8) * SROW + col + 1] = fmaxf(acc[j][3] + by, 0.f);
        }
    }
    __syncthreads();

    // ---- pool: 4 groups x 128 col-pairs -> A2 = [h0 | mean(h1)] split bf16 ----
    if (tid < 512) {
        int cp = tid & 127, g = tid >> 7;
        int ccol = cp * 2;
        const float* rp = sacc + (size_t)(g * 12) * SROW + ccol;
        float h0x = rp[0], h0y = rp[1];
        float sx = 0.f, sy = 0.f;
#pragma unroll
        for (int r = 1; r <= F1N; r++) {
            sx += rp[r * SROW];
            sy += rp[r * SROW + 1];
        }
        size_t ob = (size_t)(b0 + g) * 512 + ccol;
        split_store2(g_A2h, g_A2l, ob, h0x, h0y);
        split_store2(g_A2h, g_A2l, ob + 256, sx * 0.1f, sy * 0.1f);
    }
}

// ---------------- GEMM2: out = A2 @ W2 + b2 (unchanged, known-good) ----------------
template <int BM, int BN, int KTOT, int WM, int WN>
__global__ __launch_bounds__((BM / WM) * (BN / WN) * 32)
void gemm_mma(const __nv_bfloat16* __restrict__ Ah_g, const __nv_bfloat16* __restrict__ Al_g,
              const __nv_bfloat16* __restrict__ Bh_g, const __nv_bfloat16* __restrict__ Bl_g,
              const float* __restrict__ bias, float* __restrict__ C) {
    constexpr int NTH = (BM / WM) * (BN / WN) * 32;
    constexpr int NCH = KTOT / 64;
    constexpr int SA = BM * 128;
    constexpr int SB = BN * 128;
    constexpr int STAGE = 2 * SA + 2 * SB;
    constexpr int NWN = BN / WN;
    constexpr int MT = WM / 16;
    constexpr int NT8 = WN / 8;
    constexpr int NT16 = WN / 16;

    extern __shared__ char smem[];
    const uint32_t sb = smem_u32(smem);
    const int tid = threadIdx.x, wid = tid >> 5, lane = tid & 31;
    const int row0 = blockIdx.x * BM, col0 = blockIdx.y * BN;
    const int wm = (wid / NWN) * WM;
    const int wn = (wid % NWN) * WN;

    float acc[MT][NT8][4];
#pragma unroll
    for (int mi = 0; mi < MT; mi++)
#pragma unroll
        for (int j = 0; j < NT8; j++)
#pragma unroll
            for (int q = 0; q < 4; q++) acc[mi][j][q] = 0.f;

    auto load_stage = [&](int c, int s) {
        const int kofs = c * 64;
        const uint32_t base = sb + s * STAGE;
#pragma unroll
        for (int i = tid; i < BM * 8; i += NTH) {
            int r = i >> 3, cc = i & 7;
            uint32_t sw = r * 128 + ((cc ^ (r & 7)) << 4);
            size_t go = (size_t)(row0 + r) * KTOT + kofs + cc * 8;
            cp16(base + sw, Ah_g + go);
            cp16(base + SA + sw, Al_g + go);
        }
#pragma unroll
        for (int i = tid; i < BN * 8; i += NTH) {
            int r = i >> 3, cc = i & 7;
            uint32_t sw = r * 128 + ((cc ^ (r & 7)) << 4);
            size_t go = (size_t)(col0 + r) * KTOT + kofs + cc * 8;
            cp16(base + 2 * SA + sw, Bh_g + go);
            cp16(base + 2 * SA + SB + sw, Bl_g + go);
        }
    };

    load_stage(0, 0);
    CP_COMMIT();

    for (int c = 0; c < NCH; c++) {
        const int s = c & 1;
        if (c + 1 < NCH) {
            load_stage(c + 1, s ^ 1);
            CP_COMMIT();
            CP_WAIT(1);
        } else {
            CP_WAIT(0);
        }
        __syncthreads();
        const uint32_t base = sb + s * STAGE;

#pragma unroll
        for (int k16 = 0; k16 < 4; k16++) {
            const int cc = k16 * 2 + (lane >> 4);
            uint32_t ah[MT][4], al[MT][4], bh[NT16][4], bl[NT16][4];
#pragma unroll
            for (int mi = 0; mi < MT; mi++) {
                int r = wm + mi * 16 + (lane & 15);
                uint32_t ad = base + r * 128 + ((cc ^ (r & 7)) << 4);
                ldsm4(ah[mi], ad);
                ldsm4(al[mi], ad + SA);
            }
#pragma unroll
            for (int ni = 0; ni < NT16; ni++) {
                int r = wn + ni * 16 + (lane & 15);
                uint32_t ad = base + 2 * SA + r * 128 + ((cc ^ (r & 7)) << 4);
                ldsm4(bh[ni], ad);
                ldsm4(bl[ni], ad + SB);
            }
#pragma unroll
            for (int mi = 0; mi < MT; mi++)
#pragma unroll
                for (int j = 0; j < NT8; j++) {
                    uint32_t bfh[2] = {bh[j >> 1][j & 1], bh[j >> 1][(j & 1) + 2]};
                    uint32_t bfl[2] = {bl[j >> 1][j & 1], bl[j >> 1][(j & 1) + 2]};
                    mma16816(acc[mi][j], ah[mi], bfh);
                    mma16816(acc[mi][j], ah[mi], bfl);
                    mma16816(acc[mi][j], al[mi], bfh);
                }
        }
        __syncthreads();
    }

    const int g = lane >> 2, q = lane & 3;
#pragma unroll
    for (int mi = 0; mi < MT; mi++)
#pragma unroll
        for (int j = 0; j < NT8; j++) {
            int ccol = col0 + wn + j * 8 + 2 * q;
            float bx = __ldg(bias + ccol), by = __ldg(bias + ccol + 1);
            int r0 = row0 + wm + mi * 16 + g;
            float2 v0 = make_float2(acc[mi][j][0] + bx, acc[mi][j][1] + by);
            float2 v1 = make_float2(acc[mi][j][2] + bx, acc[mi][j][3] + by);
            *reinterpret_cast<float2*>(&C[(size_t)r0 * 256 + ccol]) = v0;
            *reinterpret_cast<float2*>(&C[(size_t)(r0 + 8) * 256 + ccol]) = v1;
        }
}

// ---------------- launch ----------------
static constexpr int SMEM2 = 2 * (2 * 32 * 128 + 2 * 64 * 128);  // 49152

extern "C" void kernel_launch(void* const* d_in, const int* in_sizes, int n_in,
                              void* d_out, int out_size) {
    const float* x  = (const float*)d_in[0];
    const float* W1 = (const float*)d_in[1];
    const float* b1 = (const float*)d_in[2];
    const float* W2 = (const float*)d_in[3];
    const float* b2 = (const float*)d_in[4];
    float* out = (float*)d_out;

    __nv_bfloat16 *a2h, *a2l, *w2h, *w2l;
    cudaGetSymbolAddress((void**)&a2h, g_A2h);
    cudaGetSymbolAddress((void**)&a2l, g_A2l);
    cudaGetSymbolAddress((void**)&w2h, g_W2hT);
    cudaGetSymbolAddress((void**)&w2l, g_W2lT);

    cudaFuncSetAttribute((const void*)fused1,
                         cudaFuncAttributeMaxDynamicSharedMemorySize, SMEM_FU);
    cudaFuncSetAttribute((const void*)gemm_mma<32, 64, 512, 32, 16>,
                         cudaFuncAttributeMaxDynamicSharedMemorySize, SMEM2);

    // K0: tiled weight split/transpose
    k_convw<<<192, dim3(32, 8)>>>(W1, W2);
    // fused reduce + GEMM1 + pool -> A2 (512 CTAs x 4 groups)
    fused1<<<BB / 4, 640, SMEM_FU>>>(reinterpret_cast<const float4*>(x), b1);
    // GEMM2: out = A2 @ W2 + b2
    gemm_mma<32, 64, 512, 32, 16>
        <<<dim3(BB / 32, 4), 128, SMEM2>>>(a2h, a2l, w2h, w2l, b2, out);
}

// round 9
// speedup vs baseline: 1.8716x; 1.8716x over previous
#include <cuda_runtime.h>
#include <cuda_bf16.h>
#include <cstdint>

// ---------------- problem constants ----------------
#define BB    2048
#define F1N   10
#define F2N   25
#define NTOK  261
#define D4    32
#define GRP   12                 // rows per batch group (h0 + 10*h1 + 1 dummy)
#define MPAD  (BB * GRP)         // 24576 padded GEMM1 rows

// ---------------- scratch (device globals, allocation-free) ----------------
__device__ __align__(16) __nv_bfloat16 g_Ah[MPAD * 256];
__device__ __align__(16) __nv_bfloat16 g_Al[MPAD * 256];
__device__ __align__(16) __nv_bfloat16 g_A2h[BB * 512];
__device__ __align__(16) __nv_bfloat16 g_A2l[BB * 512];
__device__ __align__(16) __nv_bfloat16 g_W1hT[256 * 256];
__device__ __align__(16) __nv_bfloat16 g_W1lT[256 * 256];
__device__ __align__(16) __nv_bfloat16 g_W2hT[256 * 512];
__device__ __align__(16) __nv_bfloat16 g_W2lT[256 * 512];

// ---------------- PTX helpers (base sm_100-safe) ----------------
__device__ __forceinline__ uint32_t smem_u32(const void* p) {
    uint32_t a;
    asm("{ .reg .u64 t; cvta.to.shared.u64 t, %1; cvt.u32.u64 %0, t; }" : "=r"(a) : "l"(p));
    return a;
}
__device__ __forceinline__ void cp16(uint32_t s, const void* g) {
    asm volatile("cp.async.cg.shared.global [%0], [%1], 16;" :: "r"(s), "l"(g));
}
#define CP_COMMIT() asm volatile("cp.async.commit_group;" ::: "memory")
#define CP_WAIT(n)  asm volatile("cp.async.wait_group %0;" :: "n"(n) : "memory")

__device__ __forceinline__ void ldsm4(uint32_t* r, uint32_t addr) {
    asm volatile("ldmatrix.sync.aligned.m8n8.x4.shared.b16 {%0,%1,%2,%3}, [%4];"
                 : "=r"(r[0]), "=r"(r[1]), "=r"(r[2]), "=r"(r[3]) : "r"(addr));
}
__device__ __forceinline__ void mma16816(float* c, const uint32_t* a, const uint32_t* b) {
    asm volatile(
        "mma.sync.aligned.m16n8k16.row.col.f32.bf16.bf16.f32 "
        "{%0,%1,%2,%3}, {%4,%5,%6,%7}, {%8,%9}, {%0,%1,%2,%3};"
        : "+f"(c[0]), "+f"(c[1]), "+f"(c[2]), "+f"(c[3])
        : "r"(a[0]), "r"(a[1]), "r"(a[2]), "r"(a[3]), "r"(b[0]), "r"(b[1]));
}

// ---------------- bf16 split helpers ----------------
__device__ __forceinline__ void split1(float w, unsigned short& h, unsigned short& l) {
    __nv_bfloat16 hb = __float2bfloat16_rn(w);
    float r = w - __bfloat162float(hb);
    __nv_bfloat16 lb = __float2bfloat16_rn(r);
    h = __bfloat16_as_ushort(hb);
    l = __bfloat16_as_ushort(lb);
}
__device__ __forceinline__ void split_store2(__nv_bfloat16* H, __nv_bfloat16* L,
                                             size_t idx, float a, float b) {
    unsigned short h0, l0, h1, l1;
    split1(a, h0, l0);
    split1(b, h1, l1);
    *reinterpret_cast<uint32_t*>(H + idx) = (uint32_t)h0 | ((uint32_t)h1 << 16);
    *reinterpret_cast<uint32_t*>(L + idx) = (uint32_t)l0 | ((uint32_t)l1 << 16);
}
__device__ __forceinline__ void split_store4(__nv_bfloat16* H, __nv_bfloat16* L,
                                             size_t idx, float4 v) {
    unsigned short hs[4], ls[4];
    float f[4] = {v.x, v.y, v.z, v.w};
#pragma unroll
    for (int i = 0; i < 4; i++) split1(f[i], hs[i], ls[i]);
    *reinterpret_cast<uint2*>(H + idx) =
        make_uint2((uint32_t)hs[0] | ((uint32_t)hs[1] << 16),
                   (uint32_t)hs[2] | ((uint32_t)hs[3] << 16));
    *reinterpret_cast<uint2*>(L + idx) =
        make_uint2((uint32_t)ls[0] | ((uint32_t)ls[1] << 16),
                   (uint32_t)ls[2] | ((uint32_t)ls[3] << 16));
}

// ---------------- K1: merged weight-prep + neighbor-mean reduce ----------------
// Blocks 0..191: 32x32 tiled transpose+split of W1/W2 (coalesced both sides).
// Blocks 192.. : reduce -> split bf16 A rows (12-row padded groups).
#define CONVW_BLOCKS 192
__global__ __launch_bounds__(256)
void k_prep(const float4* __restrict__ x4,
            const float* __restrict__ W1, const float* __restrict__ W2) {
    __shared__ float tile[32][33];
    if (blockIdx.x < CONVW_BLOCKS) {
        int t = blockIdx.x;
        const float* W;
        __nv_bfloat16 *OH, *OL;
        int KD, ND, tk, tn;
        if (t < 64) {
            W = W1; OH = g_W1hT; OL = g_W1lT; KD = 256; ND = 256;
            tk = t >> 3; tn = t & 7;
        } else {
            t -= 64;
            W = W2; OH = g_W2hT; OL = g_W2lT; KD = 512; ND = 256;
            tk = t >> 3; tn = t & 7;
        }
        int x = threadIdx.x & 31, y0 = threadIdx.x >> 5;
#pragma unroll
        for (int yy = 0; yy < 4; yy++) {
            int k = tk * 32 + y0 * 4 + yy;
            tile[y0 * 4 + yy][x] = W[(size_t)k * ND + tn * 32 + x];
        }
        __syncthreads();
#pragma unroll
        for (int yy = 0; yy < 4; yy++) {
            int n = tn * 32 + y0 * 4 + yy;
            float v = tile[x][y0 * 4 + yy];
            unsigned short h, l;
            split1(v, h, l);
            size_t o = (size_t)n * KD + tk * 32 + x;
            OH[o] = __ushort_as_bfloat16(h);
            OL[o] = __ushort_as_bfloat16(l);
        }
        return;
    }

    const int HOP2_SLOTS = BB * F1N * D4;  // 655360
    int idx = (blockIdx.x - CONVW_BLOCKS) * blockDim.x + threadIdx.x;
    if (idx < HOP2_SLOTS) {
        int d4 = idx & 31;
        int fg = idx >> 5;
        int f = fg % F1N;
        int b = fg / F1N;
        const float4* p = x4 + (size_t)b * NTOK * D4 + (size_t)(1 + F1N + f * F2N) * D4 + d4;
        float4 s[5];
#pragma unroll
        for (int j = 0; j < 5; j++) s[j] = make_float4(0.f, 0.f, 0.f, 0.f);
#pragma unroll
        for (int kb = 0; kb < 5; kb++) {
#pragma unroll
            for (int j = 0; j < 5; j++) {
                float4 v = p[(size_t)(kb * 5 + j) * D4];
                s[j].x += v.x; s[j].y += v.y; s[j].z += v.z; s[j].w += v.w;
            }
        }
        float4 tot = make_float4(
            s[0].x + s[1].x + s[2].x + s[3].x + s[4].x,
            s[0].y + s[1].y + s[2].y + s[3].y + s[4].y,
            s[0].z + s[1].z + s[2].z + s[3].z + s[4].z,
            s[0].w + s[1].w + s[2].w + s[3].w + s[4].w);
        const float inv = 1.0f / (float)F2N;
        size_t row = (size_t)b * GRP + 1 + f;
        split_store4(g_Ah, g_Al, row * 256 + 128 + d4 * 4,
                     make_float4(tot.x * inv, tot.y * inv, tot.z * inv, tot.w * inv));
    } else {
        int j = idx - HOP2_SLOTS;
        if (j >= BB * D4) return;
        int d4 = j & 31;
        int b = j >> 5;
        const float4* p = x4 + (size_t)b * NTOK * D4;
        size_t base = (size_t)b * GRP;
        split_store4(g_Ah, g_Al, base * 256 + d4 * 4, p[d4]);  // seed
        float4 s0 = make_float4(0.f, 0.f, 0.f, 0.f), s1 = s0;
#pragma unroll
        for (int f = 0; f < F1N; f += 2) {
            float4 v0 = p[(size_t)(1 + f) * D4 + d4];
            float4 v1 = p[(size_t)(2 + f) * D4 + d4];
            split_store4(g_Ah, g_Al, (base + 1 + f) * 256 + d4 * 4, v0);
            split_store4(g_Ah, g_Al, (base + 2 + f) * 256 + d4 * 4, v1);
            s0.x += v0.x; s0.y += v0.y; s0.z += v0.z; s0.w += v0.w;
            s1.x += v1.x; s1.y += v1.y; s1.z += v1.z; s1.w += v1.w;
        }
        const float inv = 1.0f / (float)F1N;
        split_store4(g_Ah, g_Al, base * 256 + 128 + d4 * 4,
                     make_float4((s0.x + s1.x) * inv, (s0.y + s1.y) * inv,
                                 (s0.z + s1.z) * inv, (s0.w + s1.w) * inv));
        uint2 z = make_uint2(0u, 0u);
        *reinterpret_cast<uint2*>(g_Ah + (base + 11) * 256 + d4 * 4) = z;
        *reinterpret_cast<uint2*>(g_Al + (base + 11) * 256 + d4 * 4) = z;
        *reinterpret_cast<uint2*>(g_Ah + (base + 11) * 256 + 128 + d4 * 4) = z;
        *reinterpret_cast<uint2*>(g_Al + (base + 11) * 256 + 128 + d4 * 4) = z;
    }
}

// ---------------- GEMM1 fused with pooling, full-N (A read once) ----------------
// BM=96 (8 groups of 12), BN=256, K=256. 384 threads = 12 warps (3M x 4N), warp 32x64.
__global__ __launch_bounds__(384)
void gemm1_fused(const float* __restrict__ bias) {
    constexpr int BM = 96, BN = 256, KTOT = 256;
    constexpr int NCH = KTOT / 64;
    constexpr int SA = BM * 128;            // 12288 per A array
    constexpr int SB = BN * 128;            // 32768 per B array
    constexpr int STAGE = 2 * SA + 2 * SB;  // 90112
    constexpr int MT = 2, NT8 = 8, NT16 = 4;
    constexpr int SROW = 258;

    extern __shared__ char smem[];
    const uint32_t sb = smem_u32(smem);
    const int tid = threadIdx.x, wid = tid >> 5, lane = tid & 31;
    const int row0 = blockIdx.x * BM;
    const int wm = (wid >> 2) * 32;   // 0,32,64
    const int wn = (wid & 3) * 64;    // 0..192

    float acc[MT][NT8][4];
#pragma unroll
    for (int mi = 0; mi < MT; mi++)
#pragma unroll
        for (int j = 0; j < NT8; j++)
#pragma unroll
            for (int q = 0; q < 4; q++) acc[mi][j][q] = 0.f;

    auto load_stage = [&](int c, int s) {
        const int kofs = c * 64;
        const uint32_t base = sb + s * STAGE;
#pragma unroll
        for (int i = tid; i < BM * 8; i += 384) {
            int r = i >> 3, cc = i & 7;
            uint32_t sw = r * 128 + ((cc ^ (r & 7)) << 4);
            size_t go = (size_t)(row0 + r) * KTOT + kofs + cc * 8;
            cp16(base + sw, g_Ah + go);
            cp16(base + SA + sw, g_Al + go);
        }
#pragma unroll
        for (int i = tid; i < BN * 8; i += 384) {
            int r = i >> 3, cc = i & 7;
            uint32_t sw = r * 128 + ((cc ^ (r & 7)) << 4);
            size_t go = (size_t)r * KTOT + kofs + cc * 8;
            cp16(base + 2 * SA + sw, g_W1hT + go);
            cp16(base + 2 * SA + SB + sw, g_W1lT + go);
        }
    };

    load_stage(0, 0);
    CP_COMMIT();

    for (int c = 0; c < NCH; c++) {
        const int s = c & 1;
        if (c + 1 < NCH) {
            load_stage(c + 1, s ^ 1);
            CP_COMMIT();
            CP_WAIT(1);
        } else {
            CP_WAIT(0);
        }
        __syncthreads();
        const uint32_t base = sb + s * STAGE;

#pragma unroll
        for (int k16 = 0; k16 < 4; k16++) {
            const int cc = k16 * 2 + (lane >> 4);
            uint32_t ah[MT][4], al[MT][4], bh[NT16][4], bl[NT16][4];
#pragma unroll
            for (int mi = 0; mi < MT; mi++) {
                int r = wm + mi * 16 + (lane & 15);
                uint32_t ad = base + r * 128 + ((cc ^ (r & 7)) << 4);
                ldsm4(ah[mi], ad);
                ldsm4(al[mi], ad + SA);
            }
#pragma unroll
            for (int ni = 0; ni < NT16; ni++) {
                int r = wn + ni * 16 + (lane & 15);
                uint32_t ad = base + 2 * SA + r * 128 + ((cc ^ (r & 7)) << 4);
                ldsm4(bh[ni], ad);
                ldsm4(bl[ni], ad + SB);
            }
#pragma unroll
            for (int mi = 0; mi < MT; mi++)
#pragma unroll
                for (int j = 0; j < NT8; j++) {
                    uint32_t bfh[2] = {bh[j >> 1][j & 1], bh[j >> 1][(j & 1) + 2]};
                    uint32_t bfl[2] = {bl[j >> 1][j & 1], bl[j >> 1][(j & 1) + 2]};
                    mma16816(acc[mi][j], ah[mi], bfh);
                    mma16816(acc[mi][j], ah[mi], bfl);
                    mma16816(acc[mi][j], al[mi], bfh);
                }
        }
        __syncthreads();
    }

    // epilogue: acc (+bias, ReLU) -> smem fp32 tile [96][258]
    float* sacc = reinterpret_cast<float*>(smem);
    const int g = lane >> 2, q = lane & 3;
#pragma unroll
    for (int mi = 0; mi < MT; mi++)
#pragma unroll
        for (int j = 0; j < NT8; j++) {
            int ccol = wn + j * 8 + 2 * q;
            float bx = __ldg(bias + ccol);
            float by = __ldg(bias + ccol + 1);
            int r = wm + mi * 16 + g;
            sacc[r * SROW + ccol]           = fmaxf(acc[mi][j][0] + bx, 0.f);
            sacc[r * SROW + ccol + 1]       = fmaxf(acc[mi][j][1] + by, 0.f);
            sacc[(r + 8) * SROW + ccol]     = fmaxf(acc[mi][j][2] + bx, 0.f);
            sacc[(r + 8) * SROW + ccol + 1] = fmaxf(acc[mi][j][3] + by, 0.f);
        }
    __syncthreads();

    // pool: 8 groups x 128 col-pairs -> A2 = [h0 | mean(h1)] split bf16 (full 512 row)
#pragma unroll 1
    for (int i = tid; i < 8 * 128; i += 384) {
        int cp = i & 127;
        int grp = i >> 7;
        int c = cp * 2;
        int b = blockIdx.x * 8 + grp;
        const float* rowp = sacc + grp * 12 * SROW + c;
        float h0x = rowp[0], h0y = rowp[1];
        float sx = 0.f, sy = 0.f;
#pragma unroll
        for (int r = 1; r <= 10; r++) {
            sx += rowp[r * SROW];
            sy += rowp[r * SROW + 1];
        }
        size_t ob = (size_t)b * 512 + c;
        split_store2(g_A2h, g_A2l, ob, h0x, h0y);
        split_store2(g_A2h, g_A2l, ob + 256, sx * 0.1f, sy * 0.1f);
    }
}

// ---------------- GEMM2: out = A2 @ W2 + b2 (round-4 known-good shape) ----------------
template <int BM, int BN, int KTOT, int WM, int WN>
__global__ __launch_bounds__((BM / WM) * (BN / WN) * 32)
void gemm_mma(const __nv_bfloat16* __restrict__ Ah_g, const __nv_bfloat16* __restrict__ Al_g,
              const __nv_bfloat16* __restrict__ Bh_g, const __nv_bfloat16* __restrict__ Bl_g,
              const float* __restrict__ bias, float* __restrict__ C) {
    constexpr int NTH = (BM / WM) * (BN / WN) * 32;
    constexpr int NCH = KTOT / 64;
    constexpr int SA = BM * 128;
    constexpr int SB = BN * 128;
    constexpr int STAGE = 2 * SA + 2 * SB;
    constexpr int NWN = BN / WN;
    constexpr int MT = WM / 16;
    constexpr int NT8 = WN / 8;
    constexpr int NT16 = WN / 16;

    extern __shared__ char smem[];
    const uint32_t sb = smem_u32(smem);
    const int tid = threadIdx.x, wid = tid >> 5, lane = tid & 31;
    const int row0 = blockIdx.x * BM, col0 = blockIdx.y * BN;
    const int wm = (wid / NWN) * WM;
    const int wn = (wid % NWN) * WN;

    float acc[MT][NT8][4];
#pragma unroll
    for (int mi = 0; mi < MT; mi++)
#pragma unroll
        for (int j = 0; j < NT8; j++)
#pragma unroll
            for (int q = 0; q < 4; q++) acc[mi][j][q] = 0.f;

    auto load_stage = [&](int c, int s) {
        const int kofs = c * 64;
        const uint32_t base = sb + s * STAGE;
#pragma unroll
        for (int i = tid; i < BM * 8; i += NTH) {
            int r = i >> 3, cc = i & 7;
            uint32_t sw = r * 128 + ((cc ^ (r & 7)) << 4);
            size_t go = (size_t)(row0 + r) * KTOT + kofs + cc * 8;
            cp16(base + sw, Ah_g + go);
            cp16(base + SA + sw, Al_g + go);
        }
#pragma unroll
        for (int i = tid; i < BN * 8; i += NTH) {
            int r = i >> 3, cc = i & 7;
            uint32_t sw = r * 128 + ((cc ^ (r & 7)) << 4);
            size_t go = (size_t)(col0 + r) * KTOT + kofs + cc * 8;
            cp16(base + 2 * SA + sw, Bh_g + go);
            cp16(base + 2 * SA + SB + sw, Bl_g + go);
        }
    };

    load_stage(0, 0);
    CP_COMMIT();

    for (int c = 0; c < NCH; c++) {
        const int s = c & 1;
        if (c + 1 < NCH) {
            load_stage(c + 1, s ^ 1);
            CP_COMMIT();
            CP_WAIT(1);
        } else {
            CP_WAIT(0);
        }
        __syncthreads();
        const uint32_t base = sb + s * STAGE;

#pragma unroll
        for (int k16 = 0; k16 < 4; k16++) {
            const int cc = k16 * 2 + (lane >> 4);
            uint32_t ah[MT][4], al[MT][4], bh[NT16][4], bl[NT16][4];
#pragma unroll
            for (int mi = 0; mi < MT; mi++) {
                int r = wm + mi * 16 + (lane & 15);
                uint32_t ad = base + r * 128 + ((cc ^ (r & 7)) << 4);
                ldsm4(ah[mi], ad);
                ldsm4(al[mi], ad + SA);
            }
#pragma unroll
            for (int ni = 0; ni < NT16; ni++) {
                int r = wn + ni * 16 + (lane & 15);
                uint32_t ad = base + 2 * SA + r * 128 + ((cc ^ (r & 7)) << 4);
                ldsm4(bh[ni], ad);
                ldsm4(bl[ni], ad + SB);
            }
#pragma unroll
            for (int mi = 0; mi < MT; mi++)
#pragma unroll
                for (int j = 0; j < NT8; j++) {
                    uint32_t bfh[2] = {bh[j >> 1][j & 1], bh[j >> 1][(j & 1) + 2]};
                    uint32_t bfl[2] = {bl[j >> 1][j & 1], bl[j >> 1][(j & 1) + 2]};
                    mma16816(acc[mi][j], ah[mi], bfh);
                    mma16816(acc[mi][j], ah[mi], bfl);
                    mma16816(acc[mi][j], al[mi], bfh);
                }
        }
        __syncthreads();
    }

    const int g = lane >> 2, q = lane & 3;
#pragma unroll
    for (int mi = 0; mi < MT; mi++)
#pragma unroll
        for (int j = 0; j < NT8; j++) {
            int ccol = col0 + wn + j * 8 + 2 * q;
            float bx = __ldg(bias + ccol), by = __ldg(bias + ccol + 1);
            int r0 = row0 + wm + mi * 16 + g;
            float2 v0 = make_float2(acc[mi][j][0] + bx, acc[mi][j][1] + by);
            float2 v1 = make_float2(acc[mi][j][2] + bx, acc[mi][j][3] + by);
            *reinterpret_cast<float2*>(&C[(size_t)r0 * 256 + ccol]) = v0;
            *reinterpret_cast<float2*>(&C[(size_t)(r0 + 8) * 256 + ccol]) = v1;
        }
}

// ---------------- launch (single stream, 3 kernels) ----------------
static constexpr int SMEM1 = 2 * (2 * 96 * 128 + 2 * 256 * 128);  // 180224
static constexpr int SMEM2 = 2 * (2 * 64 * 128 + 2 * 64 * 128);   // 65536

extern "C" void kernel_launch(void* const* d_in, const int* in_sizes, int n_in,
                              void* d_out, int out_size) {
    const float* x  = (const float*)d_in[0];
    const float* W1 = (const float*)d_in[1];
    const float* b1 = (const float*)d_in[2];
    const float* W2 = (const float*)d_in[3];
    const float* b2 = (const float*)d_in[4];
    float* out = (float*)d_out;

    __nv_bfloat16 *a2h, *a2l, *w2h, *w2l;
    cudaGetSymbolAddress((void**)&a2h, g_A2h);
    cudaGetSymbolAddress((void**)&a2l, g_A2l);
    cudaGetSymbolAddress((void**)&w2h, g_W2hT);
    cudaGetSymbolAddress((void**)&w2l, g_W2lT);

    cudaFuncSetAttribute((const void*)gemm1_fused,
                         cudaFuncAttributeMaxDynamicSharedMemorySize, SMEM1);
    cudaFuncSetAttribute((const void*)gemm_mma<64, 64, 512, 32, 16>,
                         cudaFuncAttributeMaxDynamicSharedMemorySize, SMEM2);

    // K1: merged weight prep (192 blocks) + neighbor-mean reduce (2816 blocks)
    {
        int red_total = BB * F1N * D4 + BB * D4;  // 720896
        int red_blocks = (red_total + 255) / 256; // 2816
        k_prep<<<CONVW_BLOCKS + red_blocks, 256>>>(
            reinterpret_cast<const float4*>(x), W1, W2);
    }
    // GEMM1 + pooling fused, full-N: A2 = [h0 | mean h1], grid 256
    gemm1_fused<<<MPAD / 96, 384, SMEM1>>>(b1);
    // GEMM2: out = A2 @ W2 + b2, grid 32x4, 256 thr
    gemm_mma<64, 64, 512, 32, 16>
        <<<dim3(BB / 64, 4), 256, SMEM2>>>(a2h, a2l, w2h, w2l, b2, out);
}